// round 2
// baseline (speedup 1.0000x reference)
#include <cuda_runtime.h>
#include <cstdint>

#define NROWS 384
#define DDIM  768

// Scratch for the two small GEMM outputs (A has b1 folded in).
__device__ float g_A[NROWS * DDIM];
__device__ float g_B[NROWS * DDIM];

// ---------------------------------------------------------------------------
// Phase 1: C = P @ Wt^T for the concatenated 1536 output columns.
//   col jj <  768 : g_A[i][jj] = sum_k P[i,k] * W1[jj,     k] + b1[jj]
//   col jj >= 768 : g_B[i][jj'] = sum_k P[i,k] * W1[jj',768+k]
// Tiled fp32 SIMT GEMM: BM=BN=64, BK=16, 256 threads, 4x4 per thread.
// Grid: (1536/64, 384/64) = (24, 6) = 144 CTAs (~1 wave).
// ---------------------------------------------------------------------------
__global__ void gemm_kernel(const float* __restrict__ P,
                            const float* __restrict__ W1,
                            const float* __restrict__ b1) {
    __shared__ float Ps[16][68];   // [k][i], padded for f4-aligned reads
    __shared__ float Qs[16][68];   // [k][j]

    const int t  = threadIdx.x;        // 0..255
    const int tx = t & 15;             // j micro-tile
    const int ty = t >> 4;             // i micro-tile
    const int col0 = blockIdx.x * 64;  // 0..1472
    const int row0 = blockIdx.y * 64;
    const bool isB = (col0 >= DDIM);
    // W row pointer base: W1[(col0%768) + r][ (isB?768:0) + k ]
    const float* Wbase = W1 + (isB ? (size_t)(col0 - DDIM) * (2 * DDIM) + DDIM
                                   : (size_t)col0 * (2 * DDIM));

    const int lr  = t >> 2;            // 0..63  (tile row for loads)
    const int lc4 = (t & 3) << 2;      // 0,4,8,12 (k-chunk for loads)

    float acc[4][4];
#pragma unroll
    for (int a = 0; a < 4; a++)
#pragma unroll
        for (int b = 0; b < 4; b++) acc[a][b] = 0.0f;

    for (int k0 = 0; k0 < DDIM; k0 += 16) {
        // Load P tile [64 rows x 16 k], one float4 per thread, transpose-store.
        float4 pv = *(const float4*)(P + (size_t)(row0 + lr) * DDIM + k0 + lc4);
        Ps[lc4 + 0][lr] = pv.x; Ps[lc4 + 1][lr] = pv.y;
        Ps[lc4 + 2][lr] = pv.z; Ps[lc4 + 3][lr] = pv.w;
        // Load W tile [64 out-cols x 16 k].
        float4 wv = *(const float4*)(Wbase + (size_t)lr * (2 * DDIM) + k0 + lc4);
        Qs[lc4 + 0][lr] = wv.x; Qs[lc4 + 1][lr] = wv.y;
        Qs[lc4 + 2][lr] = wv.z; Qs[lc4 + 3][lr] = wv.w;
        __syncthreads();

#pragma unroll
        for (int k = 0; k < 16; k++) {
            float4 av = *(const float4*)&Ps[k][ty << 2];
            float4 bv = *(const float4*)&Qs[k][tx << 2];
            float aa[4] = {av.x, av.y, av.z, av.w};
            float bb[4] = {bv.x, bv.y, bv.z, bv.w};
#pragma unroll
            for (int a = 0; a < 4; a++)
#pragma unroll
                for (int b = 0; b < 4; b++)
                    acc[a][b] = fmaf(aa[a], bb[b], acc[a][b]);
        }
        __syncthreads();
    }

    const int cbase = isB ? (col0 - DDIM) : col0;
    float* dst = isB ? g_B : g_A;
#pragma unroll
    for (int a = 0; a < 4; a++) {
        const int i = row0 + (ty << 2) + a;
#pragma unroll
        for (int b = 0; b < 4; b++) {
            const int j = cbase + (tx << 2) + b;
            float v = acc[a][b];
            if (!isB) v += b1[j];
            dst[(size_t)i * DDIM + j] = v;
        }
    }
}

// ---------------------------------------------------------------------------
// Phase 2: fused  out[i,j,c] = sum_d tanh(g_A[i,d] + g_B[j,d]) * W2[c,d] + b2[c]
// CTA tile: 16 i x 64 j, 256 threads (tx=0..15 -> j = tx + 16*jj, ty=0..15 -> i).
// d processed in smem chunks of 64. Row stride 69 (= 5 mod 32, odd) makes the
// inner per-jj Bs reads conflict-free across the 16 tx lanes.
// Grid: (384/64, 384/16) = (6, 24) = 144 CTAs.
// MUFU.TANH-bound: target 16 elem/cyc/SM.
// ---------------------------------------------------------------------------
#define TI 16
#define TJ 64
#define SP 69

__global__ void pair_kernel(const float* __restrict__ W2,
                            const float* __restrict__ b2,
                            float* __restrict__ out) {
    __shared__ float As[TI][SP];
    __shared__ float Bs[TJ][SP];
    __shared__ float W0s[64];
    __shared__ float W1s[64];

    const int t  = threadIdx.x;   // 0..255
    const int tx = t & 15;
    const int ty = t >> 4;
    const int i0 = blockIdx.y * TI;
    const int j0 = blockIdx.x * TJ;

    float acc0[4] = {0.f, 0.f, 0.f, 0.f};
    float acc1[4] = {0.f, 0.f, 0.f, 0.f};

    for (int d0 = 0; d0 < DDIM; d0 += 64) {
        // Fill As: 16x64 floats = 256 float4 -> 1 per thread.
        {
            const int row = t >> 4, c4 = (t & 15) << 2;
            float4 v = *(const float4*)(g_A + (size_t)(i0 + row) * DDIM + d0 + c4);
            As[row][c4 + 0] = v.x; As[row][c4 + 1] = v.y;
            As[row][c4 + 2] = v.z; As[row][c4 + 3] = v.w;
        }
        // Fill Bs: 64x64 floats = 1024 float4 -> 4 per thread.
#pragma unroll
        for (int r = 0; r < 4; r++) {
            const int f = t + 256 * r;
            const int row = f >> 4, c4 = (f & 15) << 2;
            float4 v = *(const float4*)(g_B + (size_t)(j0 + row) * DDIM + d0 + c4);
            Bs[row][c4 + 0] = v.x; Bs[row][c4 + 1] = v.y;
            Bs[row][c4 + 2] = v.z; Bs[row][c4 + 3] = v.w;
        }
        // Fill W2 chunk (2 x 64).
        if (t < 16) {
            const int c4 = t << 2;
            float4 v = *(const float4*)(W2 + d0 + c4);
            W0s[c4 + 0] = v.x; W0s[c4 + 1] = v.y; W0s[c4 + 2] = v.z; W0s[c4 + 3] = v.w;
        } else if (t < 32) {
            const int c4 = (t - 16) << 2;
            float4 v = *(const float4*)(W2 + DDIM + d0 + c4);
            W1s[c4 + 0] = v.x; W1s[c4 + 1] = v.y; W1s[c4 + 2] = v.z; W1s[c4 + 3] = v.w;
        }
        __syncthreads();

#pragma unroll 4
        for (int dk = 0; dk < 64; dk++) {
            const float a  = As[ty][dk];
            const float w0 = W0s[dk];
            const float w1 = W1s[dk];
#pragma unroll
            for (int jj = 0; jj < 4; jj++) {
                const float b = Bs[tx + 16 * jj][dk];
                const float x = a + b;
                float th;
                asm("tanh.approx.f32 %0, %1;" : "=f"(th) : "f"(x));
                acc0[jj] = fmaf(th, w0, acc0[jj]);
                acc1[jj] = fmaf(th, w1, acc1[jj]);
            }
        }
        __syncthreads();
    }

    const float bb0 = b2[0];
    const float bb1 = b2[1];
    const int i = i0 + ty;
#pragma unroll
    for (int jj = 0; jj < 4; jj++) {
        const int j = j0 + tx + 16 * jj;
        float2 v = make_float2(acc0[jj] + bb0, acc1[jj] + bb1);
        *(float2*)(out + ((size_t)i * NROWS + j) * 2) = v;
    }
}

// ---------------------------------------------------------------------------
extern "C" void kernel_launch(void* const* d_in, const int* in_sizes, int n_in,
                              void* d_out, int out_size) {
    const float* P  = (const float*)d_in[0];   // [384, 768]
    const float* W1 = (const float*)d_in[1];   // [768, 1536]
    const float* b1 = (const float*)d_in[2];   // [768]
    const float* W2 = (const float*)d_in[3];   // [2, 768]
    const float* b2 = (const float*)d_in[4];   // [2]
    float* out = (float*)d_out;                // [384, 384, 2]

    gemm_kernel<<<dim3(24, 6), 256>>>(P, W1, b1);
    pair_kernel<<<dim3(6, 24), 256>>>(W2, b2, out);
}